// round 5
// baseline (speedup 1.0000x reference)
#include <cuda_runtime.h>
#include <stdint.h>

// ============================================================================
// ImpulseNoise — bit-exact JAX (threefry_partitionable) salt & pepper.
// key=(0,42); k_flip = tf20(key,(0,0)); k_salt = tf20(key,(0,1))
// bits(i) = fold(tf20(k, (0, i)));  u = (bits>>9)*2^-23
// u <= 0.09f  <=>  bits <= (754974<<9)|511     (rel_err=0 verified R2-R4)
// u <= 0.5    <=>  bits <= 0x800001FF
//
// R5: rotate moved off the saturated alu pipe.
//   rotl(x,r) = lo(x*2^r) | hi(x*2^r)  -> IMAD.WIDE (fma pipe)
//   round combine (lo|hi)^x0           -> ONE 3-input LOP3 (alu)
//   multipliers 2^r built at runtime from opaque `one` so ptxas cannot
//   strength-reduce the widening multiply back into SHF.
// alu-forced ops/hash: 53 -> ~23; flexible adds balanced by ptxas.
// Salt hashes remain warp-ballot-compacted (~0.09 hashes/elem).
// ============================================================================

struct U2c { unsigned a, b; };

constexpr U2c threefry20_host(unsigned k0, unsigned k1, unsigned x0, unsigned x1) {
    unsigned ks2 = k0 ^ k1 ^ 0x1BD11BDAu;
    x0 += k0; x1 += k1;
#define TFR_H(r) { x0 += x1; x1 = (x1 << (r)) | (x1 >> (32 - (r))); x1 ^= x0; }
    TFR_H(13) TFR_H(15) TFR_H(26) TFR_H(6)
    x0 += k1;  x1 += ks2 + 1u;
    TFR_H(17) TFR_H(29) TFR_H(16) TFR_H(24)
    x0 += ks2; x1 += k0 + 2u;
    TFR_H(13) TFR_H(15) TFR_H(26) TFR_H(6)
    x0 += k0;  x1 += k1 + 3u;
    TFR_H(17) TFR_H(29) TFR_H(16) TFR_H(24)
    x0 += k1;  x1 += ks2 + 4u;
    TFR_H(13) TFR_H(15) TFR_H(26) TFR_H(6)
    x0 += ks2; x1 += k0 + 5u;
#undef TFR_H
    return U2c{x0, x1};
}

constexpr U2c KFLIP = threefry20_host(0u, 42u, 0u, 0u);
constexpr U2c KSALT = threefry20_host(0u, 42u, 0u, 1u);

constexpr unsigned N_TOTAL = 64u * 3u * 512u * 512u;   // 50331648
constexpr unsigned FLIP_T  = (754974u << 9) | 511u;    // u <= 0.09f
constexpr unsigned SALT_T  = 0x800001FFu;              // u <= 0.5f

// Runtime rotation multipliers (2^r), opaque to ptxas.
struct Mults { unsigned m13, m15, m26, m6, m17, m29, m16, m24; };

// One Threefry round: x0 += x1; x1 = rotl(x1,r) ^ x0
// rotl via IMAD.WIDE (fma pipe), combine via one fused LOP3 (a|b)^c (alu).
__device__ __forceinline__ void round_w(unsigned& x0, unsigned& x1, unsigned mr) {
    x0 += x1;
    unsigned long long p = (unsigned long long)x1 * (unsigned long long)mr;
    unsigned lo = (unsigned)p;
    unsigned hi = (unsigned)(p >> 32);
    x1 = (lo | hi) ^ x0;
}

// Threefry-2x32-20, counter (0, i), returns x0^x1.
template <unsigned K0, unsigned K1>
__device__ __forceinline__ unsigned tf20_fold(unsigned i, const Mults& M) {
    constexpr unsigned KS2 = K0 ^ K1 ^ 0x1BD11BDAu;
    unsigned x1 = i + K1;
    unsigned x0 = x1 + K0;   // round-1 add with x0_init = K0 folded
    // finish round 1's rotate+xor
    {
        unsigned long long p = (unsigned long long)(i + K1) * (unsigned long long)M.m13;
        x1 = ((unsigned)p | (unsigned)(p >> 32)) ^ x0;
    }
    round_w(x0, x1, M.m15); round_w(x0, x1, M.m26); round_w(x0, x1, M.m6);
    x0 += K1;  x1 += KS2 + 1u;
    round_w(x0, x1, M.m17); round_w(x0, x1, M.m29); round_w(x0, x1, M.m16); round_w(x0, x1, M.m24);
    x0 += KS2; x1 += K0 + 2u;
    round_w(x0, x1, M.m13); round_w(x0, x1, M.m15); round_w(x0, x1, M.m26); round_w(x0, x1, M.m6);
    x0 += K0;  x1 += K1 + 3u;
    round_w(x0, x1, M.m17); round_w(x0, x1, M.m29); round_w(x0, x1, M.m16); round_w(x0, x1, M.m24);
    x0 += K1;  x1 += KS2 + 4u;
    round_w(x0, x1, M.m13); round_w(x0, x1, M.m15); round_w(x0, x1, M.m26); round_w(x0, x1, M.m6);
    x0 += KS2; x1 += K0 + 5u;
    return x0 ^ x1;
}

// 8 elements per thread; warp covers 256 consecutive elements.
__global__ void __launch_bounds__(256)
impulse_noise_kernel(const float* __restrict__ img, float* __restrict__ out,
                     unsigned one) {
    // Opaque power-of-2 rotation multipliers (warp-uniform registers).
    Mults M;
    M.m13 = one << 13; M.m15 = one << 15; M.m26 = one << 26; M.m6  = one << 6;
    M.m17 = one << 17; M.m29 = one << 29; M.m16 = one << 16; M.m24 = one << 24;

    unsigned gwarp = (blockIdx.x * 256u + threadIdx.x) >> 5;
    unsigned lane  = threadIdx.x & 31u;
    unsigned base  = gwarp * 256u;
    unsigned i0 = base + 4u * lane;
    unsigned i1 = base + 128u + 4u * lane;

    float4 v0 = *reinterpret_cast<const float4*>(img + i0);
    float4 v1 = *reinterpret_cast<const float4*>(img + i1);

    // Mandatory flip hashes (8 independent chains for ILP).
    bool fl[8];
#pragma unroll
    for (int s = 0; s < 4; ++s)
        fl[s] = tf20_fold<KFLIP.a, KFLIP.b>(i0 + (unsigned)s, M) <= FLIP_T;
#pragma unroll
    for (int s = 0; s < 4; ++s)
        fl[4 + s] = tf20_fold<KFLIP.a, KFLIP.b>(i1 + (unsigned)s, M) <= FLIP_T;

    // Owners store raw values; flipped slots overwritten after the fence.
    *reinterpret_cast<float4*>(out + i0) = v0;
    *reinterpret_cast<float4*>(out + i1) = v1;

    // Warp-uniform flip masks + prefix counts.
    unsigned m[8], cum[9];
    cum[0] = 0;
#pragma unroll
    for (int s = 0; s < 8; ++s) {
        m[s] = __ballot_sync(0xFFFFFFFFu, fl[s]);
        cum[s + 1] = cum[s] + (unsigned)__popc(m[s]);
    }
    unsigned nf = cum[8];

    __syncwarp();  // owner stores happen-before compacted overwrites

    // Compacted salt passes: 32 flips served per pass (~1 pass typical).
    for (unsigned start = 0; start < nf; start += 32u) {
        unsigned r = start + lane;
        if (r < nf) {
            unsigned mm = m[0], rbase = 0u, eoff = 0u;
#pragma unroll
            for (int w = 1; w < 8; ++w) {
                if (r >= cum[w]) {
                    mm = m[w];
                    rbase = cum[w];
                    eoff = (w < 4) ? (unsigned)w : (unsigned)w + 124u;
                }
            }
            unsigned rr = r - rbase;
            unsigned pos = 0u, c;
            c = (unsigned)__popc(mm & 0xFFFFu); if (rr >= c) { rr -= c; pos += 16u; mm >>= 16; }
            c = (unsigned)__popc(mm & 0xFFu);   if (rr >= c) { rr -= c; pos += 8u;  mm >>= 8; }
            c = (unsigned)__popc(mm & 0xFu);    if (rr >= c) { rr -= c; pos += 4u;  mm >>= 4; }
            c = (unsigned)__popc(mm & 0x3u);    if (rr >= c) { rr -= c; pos += 2u;  mm >>= 2; }
            c = mm & 1u;                        if (rr >= c) { pos += 1u; }

            unsigned gi = base + 4u * pos + eoff;
            unsigned bs = tf20_fold<KSALT.a, KSALT.b>(gi, M);
            out[gi] = (bs <= SALT_T) ? 1.0f : 0.0f;
        }
    }
}

extern "C" void kernel_launch(void* const* d_in, const int* in_sizes, int n_in,
                              void* d_out, int out_size) {
    const float* img = (const float*)d_in[0];
    float* out = (float*)d_out;
    constexpr unsigned threads = N_TOTAL / 8u;    // 6291456
    constexpr unsigned blocks  = threads / 256u;  // 24576
    impulse_noise_kernel<<<blocks, 256>>>(img, out, 1u);
}

// round 6
// speedup vs baseline: 1.1719x; 1.1719x over previous
#include <cuda_runtime.h>
#include <stdint.h>

// ============================================================================
// ImpulseNoise — bit-exact JAX (threefry_partitionable) salt & pepper.
// key=(0,42); k_flip = tf20(key,(0,0)); k_salt = tf20(key,(0,1))
// bits(i) = fold(tf20(k, (0, i)));  u = (bits>>9)*2^-23
// u <= 0.09f  <=>  bits <= (754974<<9)|511     (rel_err=0 verified R2-R5)
// u <= 0.5    <=>  bits <= 0x800001FF
//
// R6: HYBRID rotate placement. R4 (all SHF) was alu-bound at 89.6%;
// R5 (all IMAD.WIDE) went latency-bound (issue 63%, chains serialized at
// regs=32). Here exactly 10 of 20 rotates per hash use the wide-mul path
// (alternating within each 4-round block so only one wide product is live
// per chain), balancing alu (~36 ops/hash) against fma (~16 IMAD + 10 wide).
// launch_bounds(256,4) gives ptxas reg headroom for 8-chain ILP.
// Salt hashes remain warp-ballot-compacted (~0.09 hashes/elem).
// ============================================================================

struct U2c { unsigned a, b; };

constexpr U2c threefry20_host(unsigned k0, unsigned k1, unsigned x0, unsigned x1) {
    unsigned ks2 = k0 ^ k1 ^ 0x1BD11BDAu;
    x0 += k0; x1 += k1;
#define TFR_H(r) { x0 += x1; x1 = (x1 << (r)) | (x1 >> (32 - (r))); x1 ^= x0; }
    TFR_H(13) TFR_H(15) TFR_H(26) TFR_H(6)
    x0 += k1;  x1 += ks2 + 1u;
    TFR_H(17) TFR_H(29) TFR_H(16) TFR_H(24)
    x0 += ks2; x1 += k0 + 2u;
    TFR_H(13) TFR_H(15) TFR_H(26) TFR_H(6)
    x0 += k0;  x1 += k1 + 3u;
    TFR_H(17) TFR_H(29) TFR_H(16) TFR_H(24)
    x0 += k1;  x1 += ks2 + 4u;
    TFR_H(13) TFR_H(15) TFR_H(26) TFR_H(6)
    x0 += ks2; x1 += k0 + 5u;
#undef TFR_H
    return U2c{x0, x1};
}

constexpr U2c KFLIP = threefry20_host(0u, 42u, 0u, 0u);
constexpr U2c KSALT = threefry20_host(0u, 42u, 0u, 1u);

constexpr unsigned N_TOTAL = 64u * 3u * 512u * 512u;   // 50331648
constexpr unsigned FLIP_T  = (754974u << 9) | 511u;    // u <= 0.09f
constexpr unsigned SALT_T  = 0x800001FFu;              // u <= 0.5f

// Runtime rotation multipliers (2^r) for the mul-rotated rounds; opaque to ptxas.
struct Mults { unsigned m15, m6, m29, m24; };

// SHF round: x0 += x1; x1 = rotl(x1,r) ^ x0           (alu: SHF + LOP3)
#define TFR_S(r) { x0 += x1; x1 = __funnelshift_l(x1, x1, (r)); x1 ^= x0; }
// MUL round: rotl via IMAD.WIDE (fma), combine (lo|hi)^x0 one LOP3 (alu)
#define TFR_M(mr) { x0 += x1;                                                 \
    unsigned long long p = (unsigned long long)x1 * (unsigned long long)(mr);  \
    x1 = ((unsigned)p | (unsigned)(p >> 32)) ^ x0; }

// Threefry-2x32-20, counter (0, i), returns x0^x1.
template <unsigned K0, unsigned K1>
__device__ __forceinline__ unsigned tf20_fold(unsigned i, const Mults& M) {
    constexpr unsigned KS2 = K0 ^ K1 ^ 0x1BD11BDAu;
    unsigned x1 = i + K1;
    unsigned x0 = x1 + K0;   // round-1 add with x0_init = K0 folded
    x1 = __funnelshift_l(x1, x1, 13); x1 ^= x0;        // finish round 1 (SHF)
    TFR_M(M.m15) TFR_S(26) TFR_M(M.m6)
    x0 += K1;  x1 += KS2 + 1u;
    TFR_S(17) TFR_M(M.m29) TFR_S(16) TFR_M(M.m24)
    x0 += KS2; x1 += K0 + 2u;
    TFR_S(13) TFR_M(M.m15) TFR_S(26) TFR_M(M.m6)
    x0 += K0;  x1 += K1 + 3u;
    TFR_S(17) TFR_M(M.m29) TFR_S(16) TFR_M(M.m24)
    x0 += K1;  x1 += KS2 + 4u;
    TFR_S(13) TFR_M(M.m15) TFR_S(26) TFR_M(M.m6)
    x0 += KS2; x1 += K0 + 5u;
    return x0 ^ x1;
}
#undef TFR_S
#undef TFR_M

// 8 elements per thread; warp covers 256 consecutive elements.
__global__ void __launch_bounds__(256, 4)
impulse_noise_kernel(const float* __restrict__ img, float* __restrict__ out,
                     unsigned one) {
    Mults M;
    M.m15 = one << 15; M.m6 = one << 6; M.m29 = one << 29; M.m24 = one << 24;

    unsigned gwarp = (blockIdx.x * 256u + threadIdx.x) >> 5;
    unsigned lane  = threadIdx.x & 31u;
    unsigned base  = gwarp * 256u;
    unsigned i0 = base + 4u * lane;
    unsigned i1 = base + 128u + 4u * lane;

    float4 v0 = *reinterpret_cast<const float4*>(img + i0);
    float4 v1 = *reinterpret_cast<const float4*>(img + i1);

    // Mandatory flip hashes (8 independent chains for ILP).
    bool fl[8];
#pragma unroll
    for (int s = 0; s < 4; ++s)
        fl[s] = tf20_fold<KFLIP.a, KFLIP.b>(i0 + (unsigned)s, M) <= FLIP_T;
#pragma unroll
    for (int s = 0; s < 4; ++s)
        fl[4 + s] = tf20_fold<KFLIP.a, KFLIP.b>(i1 + (unsigned)s, M) <= FLIP_T;

    // Owners store raw values; flipped slots overwritten after the fence.
    *reinterpret_cast<float4*>(out + i0) = v0;
    *reinterpret_cast<float4*>(out + i1) = v1;

    // Warp-uniform flip masks + prefix counts.
    unsigned m[8], cum[9];
    cum[0] = 0;
#pragma unroll
    for (int s = 0; s < 8; ++s) {
        m[s] = __ballot_sync(0xFFFFFFFFu, fl[s]);
        cum[s + 1] = cum[s] + (unsigned)__popc(m[s]);
    }
    unsigned nf = cum[8];

    __syncwarp();  // owner stores happen-before compacted overwrites

    // Compacted salt passes: 32 flips served per pass (~1 pass typical).
    for (unsigned start = 0; start < nf; start += 32u) {
        unsigned r = start + lane;
        if (r < nf) {
            unsigned mm = m[0], rbase = 0u, eoff = 0u;
#pragma unroll
            for (int w = 1; w < 8; ++w) {
                if (r >= cum[w]) {
                    mm = m[w];
                    rbase = cum[w];
                    eoff = (w < 4) ? (unsigned)w : (unsigned)w + 124u;
                }
            }
            unsigned rr = r - rbase;
            unsigned pos = 0u, c;
            c = (unsigned)__popc(mm & 0xFFFFu); if (rr >= c) { rr -= c; pos += 16u; mm >>= 16; }
            c = (unsigned)__popc(mm & 0xFFu);   if (rr >= c) { rr -= c; pos += 8u;  mm >>= 8; }
            c = (unsigned)__popc(mm & 0xFu);    if (rr >= c) { rr -= c; pos += 4u;  mm >>= 4; }
            c = (unsigned)__popc(mm & 0x3u);    if (rr >= c) { rr -= c; pos += 2u;  mm >>= 2; }
            c = mm & 1u;                        if (rr >= c) { pos += 1u; }

            unsigned gi = base + 4u * pos + eoff;
            unsigned bs = tf20_fold<KSALT.a, KSALT.b>(gi, M);
            out[gi] = (bs <= SALT_T) ? 1.0f : 0.0f;
        }
    }
}

extern "C" void kernel_launch(void* const* d_in, const int* in_sizes, int n_in,
                              void* d_out, int out_size) {
    const float* img = (const float*)d_in[0];
    float* out = (float*)d_out;
    constexpr unsigned threads = N_TOTAL / 8u;    // 6291456
    constexpr unsigned blocks  = threads / 256u;  // 24576
    impulse_noise_kernel<<<blocks, 256>>>(img, out, 1u);
}